// round 13
// baseline (speedup 1.0000x reference)
#include <cuda_runtime.h>
#include <cuda_bf16.h>
#include <cstdint>

// Problem constants: B=2, Nr=40962, Nh=4*Nr-6=163842, Cin=128, Co=64
#define BB      2
#define NR      40962
#define NHH     163842
#define M_UP    (BB*NR)        // 81924
#define M_CONV  (BB*NHH)       // 327684
#define NCTA_CONV ((M_CONV + 127) / 128)   // 2561

// Dynamic smem: 2 stages x 48K + 4K stats reduction
#define STG_BYTES 49152
#define SMEM_DYN  (2 * STG_BYTES + 4096)

// ---------------------------------------------------------------------------
// Scratch (device globals; allocation-guard safe)
// ---------------------------------------------------------------------------
__device__ float         g_h  [(size_t)M_UP * 448];     // up output  fp32
__device__ __nv_bfloat16 g_xcc[(size_t)M_CONV * 256];   // xcat split [M_CONV][2*128]
__device__ float         g_y1 [(size_t)M_CONV * 64];    // conv1 out  fp32 (pre-BN)
__device__ __nv_bfloat16 g_wuc[448 * 256];              // up_W^T  split [448][2*128]
__device__ __nv_bfloat16 g_w1c[64 * 1792];              // w1^T    split [64][2*896]
__device__ __nv_bfloat16 g_w2c[64 * 896];               // w2^T    split [64][2*448]
__device__ float         g_stat[(size_t)NCTA_CONV * 128]; // per-CTA col sums (s|ss)
__device__ float         g_part[128 * 128];             // stage-2 partials
__device__ float         g_bn[128];                     // scale[64], shift[64]

// ---------------------------------------------------------------------------
// Helpers
// ---------------------------------------------------------------------------
__device__ __forceinline__ uint32_t su32(const void* p) {
    uint32_t a;
    asm("{ .reg .u64 t; cvta.to.shared.u64 t, %1; cvt.u32.u64 %0, t; }"
        : "=r"(a) : "l"(p));
    return a;
}

#define LDSM4(r0, r1, r2, r3, addr) \
    asm volatile("ldmatrix.sync.aligned.m8n8.x4.shared.b16 {%0,%1,%2,%3}, [%4];" \
                 : "=r"(r0), "=r"(r1), "=r"(r2), "=r"(r3) : "r"(addr))
#define LDSM2(r0, r1, addr) \
    asm volatile("ldmatrix.sync.aligned.m8n8.x2.shared.b16 {%0,%1}, [%2];" \
                 : "=r"(r0), "=r"(r1) : "r"(addr))
#define CP16(dst, srcp) \
    asm volatile("cp.async.cg.shared.global [%0], [%1], 16;" \
                 :: "r"(dst), "l"(srcp) : "memory")

__device__ __forceinline__ void mma_bf16(float* d, const uint32_t* a, const uint32_t* b) {
    asm volatile(
        "mma.sync.aligned.m16n8k16.row.col.f32.bf16.bf16.f32 "
        "{%0,%1,%2,%3}, {%4,%5,%6,%7}, {%8,%9}, {%0,%1,%2,%3};"
        : "+f"(d[0]), "+f"(d[1]), "+f"(d[2]), "+f"(d[3])
        : "r"(a[0]), "r"(a[1]), "r"(a[2]), "r"(a[3]), "r"(b[0]), "r"(b[1]));
}

__device__ __forceinline__ void splitf(float v, float& hi, float& lo) {
    hi = __bfloat162float(__float2bfloat16(v));   // rn
    lo = v - hi;                                  // exact in fp32
}
__device__ __forceinline__ uint32_t pack2(float a, float b) {
    __nv_bfloat162 t;
    t.x = __float2bfloat16(a);
    t.y = __float2bfloat16(b);
    return *reinterpret_cast<uint32_t*>(&t);
}
__device__ __forceinline__ void split4(float4 v, uint2& h, uint2& l) {
    float h0,l0,h1,l1,h2,l2,h3,l3;
    splitf(v.x,h0,l0); splitf(v.y,h1,l1); splitf(v.z,h2,l2); splitf(v.w,h3,l3);
    h = make_uint2(pack2(h0,h1), pack2(h2,h3));
    l = make_uint2(pack2(l0,l1), pack2(l2,l3));
}

// ---------------------------------------------------------------------------
// Pipelined mma.sync gather-GEMM (bf16x3 emulated fp32): out = X @ W^T + bias
// SRCF32=false: src rows packed [hi(C)|lo(C)] bf16.
// SRCF32=true : src rows are C fp32; loader stages raw fp32 and converts to
//               swizzled bf16 hi/lo tiles IN PLACE in smem (optionally applying
//               bn+lrelu first when BN=true). Tile memory map in that case is
//               row-half-blocked: [Ah r0-63 | Al r0-63 | Ah r64-127 | Al r64-127].
// wt rows packed [hi(Kt)|lo(Kt)], Kt = NJ*C.
// CTA: 128 rows x 64 cols; 8 warps = 4(row) x 2(col) of 32x32 warp tiles.
// K streamed in 64-chunks, cp.async double-buffered; per k16:
// A1B1 + A2B1 + A1B2 (A2B2 dropped, ~2^-18 rel).
// STATS: per-CTA deterministic column sum/sumsq written to g_stat.
// SWAPXY: grid = (colTiles, rowTiles) so col tiles sharing A run adjacently.
// ---------------------------------------------------------------------------
template<int C, int NJ, bool GATHER, bool STATS, bool SRCF32, bool BN, bool SWAPXY>
__global__ __launch_bounds__(256) void mma_gemm(
    const void* __restrict__ srcv,
    const __nv_bfloat16* __restrict__ wt,
    const int* __restrict__ neigh,
    const float* __restrict__ bias,
    float* __restrict__ out, int M, int ostride)
{
    constexpr int Kt  = NJ * C;
    constexpr int NH  = C / 64;
    constexpr int NCH = NJ * NH;
    extern __shared__ __align__(16) char dsm[];
    const uint32_t dbase = su32(dsm);

    const int tid  = threadIdx.x;
    const int lane = tid & 31;
    const int wid  = tid >> 5;
    const int row0 = (SWAPXY ? blockIdx.y : blockIdx.x) * 128;
    const int col0 = (SWAPXY ? blockIdx.x : blockIdx.y) * 64;
    const int warp_r = wid & 3;
    const int warp_c = wid >> 2;

    const int lr = tid >> 3;        // B loader: 0..31 rows, 16B unit q
    const int q  = tid & 7;
    const int u16 = tid & 15;       // fp32 A loader: 16 units/row, 16 rows/pass
    const int lr16 = tid >> 4;

    float bnsc[4], bnsh[4];
    if (BN) {
        int ch0 = u16 * 4;
        #pragma unroll
        for (int j2 = 0; j2 < 4; j2++) {
            bnsc[j2] = g_bn[ch0 + j2];
            bnsh[j2] = g_bn[64 + ch0 + j2];
        }
    }

    float acc[2][4][4];
    #pragma unroll
    for (int a = 0; a < 2; a++)
        #pragma unroll
        for (int b = 0; b < 4; b++)
            #pragma unroll
            for (int c = 0; c < 4; c++) acc[a][b][c] = 0.f;

    const int a_row_in = ((lane >> 3) & 1) * 8 + (lane & 7);
    const int a_kseg   = (lane >> 4);
    const int b_row_in = (lane & 7);
    const int b_kseg   = ((lane >> 3) & 1);

    auto issue_load = [&](int c, int s) {
        const int j    = c / NH;
        const int koff = (c % NH) * 64;
        const uint32_t stg = dbase + (uint32_t)s * STG_BYTES;
        if (SRCF32) {
            const float* sf = (const float*)srcv;
            #pragma unroll
            for (int i = 0; i < 8; i++) {
                int rr = lr16 + 16 * i;
                int r = row0 + rr; if (r >= M) r = M - 1;
                int nid;
                if (GATHER) {
                    int b = (r >= NHH) ? 1 : 0;
                    int n = r - b * NHH;
                    nid = b * NHH + __ldg(&neigh[n * 7 + j]);
                } else nid = r;
                const float* sp = sf + (size_t)nid * C + koff + u16 * 4;
                CP16(stg + (uint32_t)(rr * 256 + u16 * 16), sp);
            }
        } else {
            const __nv_bfloat16* sb = (const __nv_bfloat16*)srcv;
            #pragma unroll
            for (int i = 0; i < 4; i++) {
                int r = row0 + lr + 32 * i; if (r >= M) r = M - 1;
                int nid;
                if (GATHER) {
                    int b = (r >= NHH) ? 1 : 0;
                    int n = r - b * NHH;
                    nid = b * NHH + __ldg(&neigh[n * 7 + j]);
                } else nid = r;
                const __nv_bfloat16* sp = sb + (size_t)nid * (2 * C) + koff + q * 8;
                int rr = lr + 32 * i;
                uint32_t doff = (uint32_t)((rr * 8 + (q ^ (rr & 7))) << 4);
                CP16(stg + doff, sp);                   // A hi
                CP16(stg + 16384 + doff, sp + C);       // A lo
            }
        }
        #pragma unroll
        for (int t = 0; t < 2; t++) {
            int n = lr + 32 * t;
            const __nv_bfloat16* wp =
                wt + (size_t)(col0 + n) * (2 * Kt) + (size_t)j * C + koff + q * 8;
            uint32_t doff = (uint32_t)((n * 8 + (q ^ (n & 7))) << 4);
            CP16(stg + 32768 + doff, wp);           // B hi
            CP16(stg + 40960 + doff, wp + Kt);      // B lo
        }
        asm volatile("cp.async.commit_group;" ::: "memory");
    };

    issue_load(0, 0);
    for (int c = 0; c < NCH; c++) {
        if (c + 1 < NCH) {
            issue_load(c + 1, (c + 1) & 1);
            asm volatile("cp.async.wait_group 1;" ::: "memory");
        } else {
            asm volatile("cp.async.wait_group 0;" ::: "memory");
        }
        __syncthreads();
        const uint32_t stg = dbase + (uint32_t)(c & 1) * STG_BYTES;
        char* smc = dsm + (size_t)(c & 1) * STG_BYTES;

        if (SRCF32) {
            // in-place convert: fp32 [128x64] -> bf16 hi/lo tiles, per row-half
            #pragma unroll
            for (int P = 0; P < 2; P++) {
                float4 v[4];
                #pragma unroll
                for (int i = 0; i < 4; i++) {
                    int p = P * 1024 + i * 256 + tid;
                    v[i] = *(const float4*)(smc + (size_t)p * 16);
                }
                if (BN) {
                    #pragma unroll
                    for (int i = 0; i < 4; i++) {
                        float t0 = v[i].x * bnsc[0] + bnsh[0]; v[i].x = fmaxf(t0, 0.2f * t0);
                        float t1 = v[i].y * bnsc[1] + bnsh[1]; v[i].y = fmaxf(t1, 0.2f * t1);
                        float t2 = v[i].z * bnsc[2] + bnsh[2]; v[i].z = fmaxf(t2, 0.2f * t2);
                        float t3 = v[i].w * bnsc[3] + bnsh[3]; v[i].w = fmaxf(t3, 0.2f * t3);
                    }
                }
                __syncthreads();   // all reads of this half done before overwrite
                #pragma unroll
                for (int i = 0; i < 4; i++) {
                    int p = P * 1024 + i * 256 + tid;
                    int row = p >> 4;
                    int k = u16 >> 1, half = u16 & 1;
                    uint32_t ha = (uint32_t)(((row & 64) << 8)
                               + ((((row & 63) * 8 + (k ^ (row & 7))) << 4) + half * 8));
                    uint2 hh, ll; split4(v[i], hh, ll);
                    *(uint2*)(smc + ha)        = hh;
                    *(uint2*)(smc + ha + 8192) = ll;
                }
            }
            __syncthreads();
        }

        #pragma unroll
        for (int k16 = 0; k16 < 4; k16++) {
            const int kb = k16 * 2;
            uint32_t ah[2][4], al[2][4], bh[4][2], bl[4][2];
            #pragma unroll
            for (int mt = 0; mt < 2; mt++) {
                int arow = warp_r * 32 + mt * 16 + a_row_in;
                int aku  = kb + a_kseg;
                uint32_t aoff, alo;
                if (SRCF32) {
                    aoff = (uint32_t)(((arow & 64) << 8)
                         + ((((arow & 63) * 8 + (aku ^ (arow & 7)))) << 4));
                    alo = aoff + 8192;
                } else {
                    aoff = (uint32_t)((arow * 8 + (aku ^ (arow & 7))) << 4);
                    alo = aoff + 16384;
                }
                LDSM4(ah[mt][0], ah[mt][1], ah[mt][2], ah[mt][3], stg + aoff);
                LDSM4(al[mt][0], al[mt][1], al[mt][2], al[mt][3], stg + alo);
            }
            #pragma unroll
            for (int nt = 0; nt < 4; nt++) {
                int brow = warp_c * 32 + nt * 8 + b_row_in;
                int bku  = kb + b_kseg;
                uint32_t off = (uint32_t)((brow * 8 + (bku ^ (brow & 7))) << 4);
                LDSM2(bh[nt][0], bh[nt][1], stg + 32768 + off);
                LDSM2(bl[nt][0], bl[nt][1], stg + 40960 + off);
            }
            #pragma unroll
            for (int mt = 0; mt < 2; mt++)
                #pragma unroll
                for (int nt = 0; nt < 4; nt++) {
                    mma_bf16(acc[mt][nt], ah[mt], bh[nt]);
                    mma_bf16(acc[mt][nt], al[mt], bh[nt]);
                    mma_bf16(acc[mt][nt], ah[mt], bl[nt]);
                }
        }
        __syncthreads();
    }

    // ---- epilogue: fp32 stores + bias (+ per-CTA deterministic stats) ----
    float s_loc[8], ss_loc[8];
    if (STATS) {
        #pragma unroll
        for (int i = 0; i < 8; i++) { s_loc[i] = 0.f; ss_loc[i] = 0.f; }
    }
    #pragma unroll
    for (int mt = 0; mt < 2; mt++) {
        #pragma unroll
        for (int nt = 0; nt < 4; nt++) {
            int r  = row0 + warp_r * 32 + mt * 16 + (lane >> 2);
            int cc = col0 + warp_c * 32 + nt * 8 + (lane & 3) * 2;
            float bx = bias[cc], by = bias[cc + 1];
            float v0 = acc[mt][nt][0] + bx, v1 = acc[mt][nt][1] + by;
            float v2 = acc[mt][nt][2] + bx, v3 = acc[mt][nt][3] + by;
            if (r < M) {
                *(float2*)&out[(size_t)r * ostride + cc] = make_float2(v0, v1);
                if (STATS) {
                    s_loc[nt*2]   += v0; ss_loc[nt*2]   += v0 * v0;
                    s_loc[nt*2+1] += v1; ss_loc[nt*2+1] += v1 * v1;
                }
            }
            if (r + 8 < M) {
                *(float2*)&out[(size_t)(r + 8) * ostride + cc] = make_float2(v2, v3);
                if (STATS) {
                    s_loc[nt*2]   += v2; ss_loc[nt*2]   += v2 * v2;
                    s_loc[nt*2+1] += v3; ss_loc[nt*2+1] += v3 * v3;
                }
            }
        }
    }
    if (STATS) {
        #pragma unroll
        for (int i = 0; i < 8; i++) {
            #pragma unroll
            for (int st = 4; st < 32; st <<= 1) {
                s_loc[i]  += __shfl_xor_sync(0xFFFFFFFFu, s_loc[i],  st);
                ss_loc[i] += __shfl_xor_sync(0xFFFFFFFFu, ss_loc[i], st);
            }
        }
        float* sred = (float*)(dsm + 2 * STG_BYTES);   // [8w][64c] s, then ss
        __syncthreads();
        if (lane < 4) {
            #pragma unroll
            for (int i = 0; i < 8; i++) {
                int colg = warp_c * 32 + (i >> 1) * 8 + lane * 2 + (i & 1);
                sred[wid * 64 + colg]       = s_loc[i];
                sred[512 + wid * 64 + colg] = ss_loc[i];
            }
        }
        __syncthreads();
        if (tid < 64) {
            int col = tid;
            int wb  = (col >= 32) ? 4 : 0;
            float s  = sred[(wb+0)*64+col] + sred[(wb+1)*64+col]
                     + sred[(wb+2)*64+col] + sred[(wb+3)*64+col];
            float ss = sred[512+(wb+0)*64+col] + sred[512+(wb+1)*64+col]
                     + sred[512+(wb+2)*64+col] + sred[512+(wb+3)*64+col];
            g_stat[(size_t)blockIdx.x * 128 + col]      = s;
            g_stat[(size_t)blockIdx.x * 128 + 64 + col] = ss;
        }
    }
}

// ---------------------------------------------------------------------------
// Prep kernels
// ---------------------------------------------------------------------------
__global__ void tspl_kernel(const float* __restrict__ src,
                            __nv_bfloat16* __restrict__ dst, int K, int N)
{
    int idx = blockIdx.x * 256 + threadIdx.x;
    if (idx >= K * N) return;
    int k = idx / N, n = idx - k * N;
    float hi, lo; splitf(src[idx], hi, lo);
    dst[(size_t)n * 2 * K + k]     = __float2bfloat16(hi);
    dst[(size_t)n * 2 * K + K + k] = __float2bfloat16(lo);
}

__global__ __launch_bounds__(256) void build_xcat_kernel(
    const float* __restrict__ x2, const int* __restrict__ topi,
    const int* __restrict__ downi)
{
    size_t idx = (size_t)blockIdx.x * 256 + threadIdx.x;
    if (idx >= (size_t)M_CONV * 32) return;
    int q = (int)(idx & 31);
    size_t bi = idx >> 5;
    int b = (bi >= NHH) ? 1 : 0;
    int i = (int)(bi - (size_t)b * NHH);
    const float* hf = g_h + (size_t)b * NR * 448;   // flat [Nr*7][64]
    float4 v;
    if (q < 16) {
        if (i < NR) {
            int t = topi[i];
            v = ((const float4*)(hf + (size_t)t * 64))[q];
        } else {
            int jj = i - NR;
            int d0 = downi[jj * 2 + 0];
            int d1 = downi[jj * 2 + 1];
            float4 a = ((const float4*)(hf + (size_t)d0 * 64))[q];
            float4 c = ((const float4*)(hf + (size_t)d1 * 64))[q];
            v = make_float4(0.5f*(a.x+c.x), 0.5f*(a.y+c.y),
                            0.5f*(a.z+c.z), 0.5f*(a.w+c.w));
        }
    } else {
        v = ((const float4*)x2)[bi * 16 + (q - 16)];
    }
    uint2 h, l; split4(v, h, l);
    ((uint2*)g_xcc)[bi * 64 + q]      = h;
    ((uint2*)g_xcc)[bi * 64 + 32 + q] = l;
}

// ---------------------------------------------------------------------------
// BN statistics: stage-2 reduce over CTAs, then finalize (all fixed order)
// ---------------------------------------------------------------------------
__global__ __launch_bounds__(128) void stats_reduce_kernel(int ncta)
{
    int col = threadIdx.x;            // 0..127 (s|ss concatenated)
    float acc = 0.f;
    for (int p = blockIdx.x; p < ncta; p += 128)
        acc += g_stat[(size_t)p * 128 + col];
    g_part[blockIdx.x * 128 + col] = acc;
}

__global__ void stats_final_kernel(const float* __restrict__ gamma,
                                   const float* __restrict__ beta)
{
    int c = threadIdx.x;
    if (c >= 64) return;
    float s = 0.f, ss = 0.f;
    for (int p = 0; p < 128; p++) {
        s  += g_part[p * 128 + c];
        ss += g_part[p * 128 + 64 + c];
    }
    const float inv = 1.0f / (float)M_CONV;
    float mean = s * inv;
    float var  = fmaxf(ss * inv - mean * mean, 0.f);
    float sc   = gamma[c] * rsqrtf(var + 1e-5f);
    g_bn[c]      = sc;
    g_bn[64 + c] = beta[c] - mean * sc;
}

// Final in-place bn2 + lrelu on d_out
__global__ __launch_bounds__(256) void bn_act_kernel(float* __restrict__ y)
{
    size_t idx = (size_t)blockIdx.x * 256 + threadIdx.x;
    if (idx >= (size_t)M_CONV * 16) return;
    int c = ((int)idx & 15) * 4;
    float4 v = ((float4*)y)[idx];
    v.x = v.x * g_bn[c+0] + g_bn[64+c+0]; v.x = fmaxf(v.x, 0.2f * v.x);
    v.y = v.y * g_bn[c+1] + g_bn[64+c+1]; v.y = fmaxf(v.y, 0.2f * v.y);
    v.z = v.z * g_bn[c+2] + g_bn[64+c+2]; v.z = fmaxf(v.z, 0.2f * v.z);
    v.w = v.w * g_bn[c+3] + g_bn[64+c+3]; v.w = fmaxf(v.w, 0.2f * v.w);
    ((float4*)y)[idx] = v;
}

// ---------------------------------------------------------------------------
extern "C" void kernel_launch(void* const* d_in, const int* in_sizes, int n_in,
                              void* d_out, int out_size)
{
    const float* x1    = (const float*)d_in[0];
    const float* x2    = (const float*)d_in[1];
    const int*   neigh = (const int*)  d_in[2];
    const int*   topi  = (const int*)  d_in[3];
    const int*   downi = (const int*)  d_in[4];
    const float* up_W  = (const float*)d_in[5];
    const float* up_b  = (const float*)d_in[6];
    const float* w1    = (const float*)d_in[7];
    const float* b1    = (const float*)d_in[8];
    const float* g1    = (const float*)d_in[9];
    const float* be1   = (const float*)d_in[10];
    const float* w2    = (const float*)d_in[11];
    const float* b2    = (const float*)d_in[12];
    const float* g2    = (const float*)d_in[13];
    const float* be2   = (const float*)d_in[14];
    float* out = (float*)d_out;

    void *p_h, *p_xcc, *p_y1, *p_wuc, *p_w1c, *p_w2c;
    cudaGetSymbolAddress(&p_h,   g_h);
    cudaGetSymbolAddress(&p_xcc, g_xcc);
    cudaGetSymbolAddress(&p_y1,  g_y1);
    cudaGetSymbolAddress(&p_wuc, g_wuc);
    cudaGetSymbolAddress(&p_w1c, g_w1c);
    cudaGetSymbolAddress(&p_w2c, g_w2c);

    // Opt-in dynamic smem (host-side config; idempotent)
    cudaFuncSetAttribute(mma_gemm<128, 1, false, false, true, false, true>,
                         cudaFuncAttributeMaxDynamicSharedMemorySize, SMEM_DYN);
    cudaFuncSetAttribute(mma_gemm<128, 7, true, true, false, false, false>,
                         cudaFuncAttributeMaxDynamicSharedMemorySize, SMEM_DYN);
    cudaFuncSetAttribute(mma_gemm<64, 7, true, true, true, true, false>,
                         cudaFuncAttributeMaxDynamicSharedMemorySize, SMEM_DYN);

    // 0) weight transpose+split
    tspl_kernel<<<(128*448 + 255)/256, 256>>>(up_W, (__nv_bfloat16*)p_wuc, 128, 448);
    tspl_kernel<<<(896*64  + 255)/256, 256>>>(w1,   (__nv_bfloat16*)p_w1c, 896, 64);
    tspl_kernel<<<(448*64  + 255)/256, 256>>>(w2,   (__nv_bfloat16*)p_w2c, 448, 64);

    // 1) up GEMM: [M_UP x 448] = x1 @ up_W + up_b  (fp32 src, in-smem split;
    //    grid swapped so the 7 col-tiles sharing an A block are L2-adjacent)
    mma_gemm<128, 1, false, false, true, false, true>
        <<<dim3(7, (M_UP + 127)/128), 256, SMEM_DYN>>>(
        x1, (const __nv_bfloat16*)p_wuc, nullptr, up_b, (float*)p_h, M_UP, 448);

    // 2) upconv gather + concat + split
    build_xcat_kernel<<<(int)(((size_t)M_CONV*32 + 255)/256), 256>>>(x2, topi, downi);

    // 3) conv1 (gather GEMM, K=896) -> g_y1 (pre-BN) + fused stats partials
    mma_gemm<128, 7, true, true, false, false, false>
        <<<dim3(NCTA_CONV, 1), 256, SMEM_DYN>>>(
        (const void*)p_xcc, (const __nv_bfloat16*)p_w1c,
        neigh, b1, (float*)p_y1, M_CONV, 64);

    // 4) bn1 stats finalize
    stats_reduce_kernel<<<128, 128>>>(NCTA_CONV);
    stats_final_kernel<<<1, 64>>>(g1, be1);

    // 5) conv2 (gather GEMM, K=448) -> d_out (pre-BN) + fused stats partials;
    //    reads fp32 g_y1 directly, applying bn1+lrelu during in-smem convert
    mma_gemm<64, 7, true, true, true, true, false>
        <<<dim3(NCTA_CONV, 1), 256, SMEM_DYN>>>(
        (const void*)p_y1, (const __nv_bfloat16*)p_w2c,
        neigh, b2, out, M_CONV, 64);

    // 6) bn2 stats finalize + final activation in place
    stats_reduce_kernel<<<128, 128>>>(NCTA_CONV);
    stats_final_kernel<<<1, 64>>>(g2, be2);
    bn_act_kernel<<<(int)(((size_t)M_CONV*16 + 255)/256), 256>>>(out);
}

// round 16
// speedup vs baseline: 1.5516x; 1.5516x over previous
#include <cuda_runtime.h>
#include <cuda_bf16.h>
#include <cstdint>

// Problem constants: B=2, Nr=40962, Nh=4*Nr-6=163842, Cin=128, Co=64
#define BB      2
#define NR      40962
#define NHH     163842
#define M_UP    (BB*NR)        // 81924
#define M_CONV  (BB*NHH)       // 327684
#define NCTA_CONV ((M_CONV + 127) / 128)   // 2561

// Dynamic smem: 2 stages x (Ah 16K | Al 16K | Bh 8K | Bl 8K) + 4K stats red
#define STG_BYTES 49152
#define SMEM_DYN  (2 * STG_BYTES + 4096)

// ---------------------------------------------------------------------------
// Scratch (device globals; allocation-guard safe)
// Packed hi|lo bf16 rows: row of C channels occupies 2C bf16 (hi[0..C), lo[C..2C))
// ---------------------------------------------------------------------------
__device__ __nv_bfloat16 g_x1c[(size_t)M_UP * 256];     // x1 split   [M_UP][2*128]
__device__ float         g_h  [(size_t)M_UP * 448];     // up output  fp32
__device__ __nv_bfloat16 g_xcc[(size_t)M_CONV * 256];   // xcat split [M_CONV][2*128]
__device__ float         g_y1 [(size_t)M_CONV * 64];    // conv1 out  fp32 (pre-BN)
__device__ __nv_bfloat16 g_y2c[(size_t)M_CONV * 128];   // bn1(y1) split [M_CONV][2*64]
__device__ __nv_bfloat16 g_wuc[448 * 256];              // up_W^T  split [448][2*128]
__device__ __nv_bfloat16 g_w1c[64 * 1792];              // w1^T    split [64][2*896]
__device__ __nv_bfloat16 g_w2c[64 * 896];               // w2^T    split [64][2*448]
__device__ float         g_stat[(size_t)NCTA_CONV * 128]; // per-CTA col sums (s|ss)
__device__ float         g_part[128 * 128];             // stage-2 partials
__device__ float         g_bn[128];                     // scale[64], shift[64]

// ---------------------------------------------------------------------------
// Helpers
// ---------------------------------------------------------------------------
__device__ __forceinline__ uint32_t su32(const void* p) {
    uint32_t a;
    asm("{ .reg .u64 t; cvta.to.shared.u64 t, %1; cvt.u32.u64 %0, t; }"
        : "=r"(a) : "l"(p));
    return a;
}

#define LDSM4(r0, r1, r2, r3, addr) \
    asm volatile("ldmatrix.sync.aligned.m8n8.x4.shared.b16 {%0,%1,%2,%3}, [%4];" \
                 : "=r"(r0), "=r"(r1), "=r"(r2), "=r"(r3) : "r"(addr))
#define LDSM2(r0, r1, addr) \
    asm volatile("ldmatrix.sync.aligned.m8n8.x2.shared.b16 {%0,%1}, [%2];" \
                 : "=r"(r0), "=r"(r1) : "r"(addr))
#define CP16(dst, srcp) \
    asm volatile("cp.async.cg.shared.global [%0], [%1], 16;" \
                 :: "r"(dst), "l"(srcp) : "memory")

__device__ __forceinline__ void mma_bf16(float* d, const uint32_t* a, const uint32_t* b) {
    asm volatile(
        "mma.sync.aligned.m16n8k16.row.col.f32.bf16.bf16.f32 "
        "{%0,%1,%2,%3}, {%4,%5,%6,%7}, {%8,%9}, {%0,%1,%2,%3};"
        : "+f"(d[0]), "+f"(d[1]), "+f"(d[2]), "+f"(d[3])
        : "r"(a[0]), "r"(a[1]), "r"(a[2]), "r"(a[3]), "r"(b[0]), "r"(b[1]));
}

__device__ __forceinline__ void splitf(float v, float& hi, float& lo) {
    hi = __bfloat162float(__float2bfloat16(v));   // rn
    lo = v - hi;                                  // exact in fp32
}
__device__ __forceinline__ uint32_t pack2(float a, float b) {
    __nv_bfloat162 t;
    t.x = __float2bfloat16(a);
    t.y = __float2bfloat16(b);
    return *reinterpret_cast<uint32_t*>(&t);
}
__device__ __forceinline__ void split4(float4 v, uint2& h, uint2& l) {
    float h0,l0,h1,l1,h2,l2,h3,l3;
    splitf(v.x,h0,l0); splitf(v.y,h1,l1); splitf(v.z,h2,l2); splitf(v.w,h3,l3);
    h = make_uint2(pack2(h0,h1), pack2(h2,h3));
    l = make_uint2(pack2(l0,l1), pack2(l2,l3));
}

// ---------------------------------------------------------------------------
// Pipelined mma.sync gather-GEMM (bf16x3 emulated fp32): out = X @ W^T + bias
// src rows packed [hi(C)|lo(C)] bf16; wt rows packed [hi(Kt)|lo(Kt)], Kt = NJ*C.
// CTA: 128 rows x 64 cols; 8 warps = 4(row) x 2(col) of 32x32 warp tiles.
// K streamed in 64-chunks, cp.async double-buffered (2 stages); per k16:
// A1B1 + A2B1 + A1B2 (A2B2 dropped, ~2^-18 rel).
// STATS: per-CTA deterministic column sum/sumsq written to g_stat.
// SWAPXY: grid = (colTiles, rowTiles) so col tiles sharing an A block are
//         launch-adjacent (L2 reuse of A across the 7 up-GEMM column tiles).
// ---------------------------------------------------------------------------
template<int C, int NJ, bool GATHER, bool STATS, bool SWAPXY>
__global__ __launch_bounds__(256) void mma_gemm(
    const __nv_bfloat16* __restrict__ src,
    const __nv_bfloat16* __restrict__ wt,
    const int* __restrict__ neigh,
    const float* __restrict__ bias,
    float* __restrict__ out, int M, int ostride)
{
    constexpr int Kt  = NJ * C;
    constexpr int NH  = C / 64;
    constexpr int NCH = NJ * NH;
    extern __shared__ __align__(16) char dsm[];
    const uint32_t dbase = su32(dsm);

    const int tid  = threadIdx.x;
    const int lane = tid & 31;
    const int wid  = tid >> 5;
    const int row0 = (SWAPXY ? blockIdx.y : blockIdx.x) * 128;
    const int col0 = (SWAPXY ? blockIdx.x : blockIdx.y) * 64;
    const int warp_r = wid & 3;
    const int warp_c = wid >> 2;

    const int lr = tid >> 3;        // 0..31 loader row
    const int q  = tid & 7;         // 16B unit

    float acc[2][4][4];
    #pragma unroll
    for (int a = 0; a < 2; a++)
        #pragma unroll
        for (int b = 0; b < 4; b++)
            #pragma unroll
            for (int c = 0; c < 4; c++) acc[a][b][c] = 0.f;

    const int a_row_in = ((lane >> 3) & 1) * 8 + (lane & 7);
    const int a_kseg   = (lane >> 4);
    const int b_row_in = (lane & 7);
    const int b_kseg   = ((lane >> 3) & 1);

    auto issue_load = [&](int c, int s) {
        const int j    = c / NH;
        const int koff = (c % NH) * 64;
        const uint32_t stg = dbase + (uint32_t)s * STG_BYTES;
        #pragma unroll
        for (int i = 0; i < 4; i++) {
            int r = row0 + lr + 32 * i; if (r >= M) r = M - 1;
            int nid;
            if (GATHER) {
                int b = (r >= NHH) ? 1 : 0;
                int n = r - b * NHH;
                nid = b * NHH + __ldg(&neigh[n * 7 + j]);
            } else nid = r;
            const __nv_bfloat16* sp = src + (size_t)nid * (2 * C) + koff + q * 8;
            int rr = lr + 32 * i;
            uint32_t doff = (uint32_t)((rr * 8 + (q ^ (rr & 7))) << 4);
            CP16(stg + doff, sp);                   // A hi
            CP16(stg + 16384 + doff, sp + C);       // A lo
        }
        #pragma unroll
        for (int t = 0; t < 2; t++) {
            int n = lr + 32 * t;
            const __nv_bfloat16* wp =
                wt + (size_t)(col0 + n) * (2 * Kt) + (size_t)j * C + koff + q * 8;
            uint32_t doff = (uint32_t)((n * 8 + (q ^ (n & 7))) << 4);
            CP16(stg + 32768 + doff, wp);           // B hi
            CP16(stg + 40960 + doff, wp + Kt);      // B lo
        }
        asm volatile("cp.async.commit_group;" ::: "memory");
    };

    issue_load(0, 0);
    for (int c = 0; c < NCH; c++) {
        if (c + 1 < NCH) {
            issue_load(c + 1, (c + 1) & 1);
            asm volatile("cp.async.wait_group 1;" ::: "memory");
        } else {
            asm volatile("cp.async.wait_group 0;" ::: "memory");
        }
        __syncthreads();
        const uint32_t stg = dbase + (uint32_t)(c & 1) * STG_BYTES;
        #pragma unroll
        for (int k16 = 0; k16 < 4; k16++) {
            const int kb = k16 * 2;
            uint32_t ah[2][4], al[2][4], bh[4][2], bl[4][2];
            #pragma unroll
            for (int mt = 0; mt < 2; mt++) {
                int arow = warp_r * 32 + mt * 16 + a_row_in;
                int aku  = kb + a_kseg;
                uint32_t off = (uint32_t)((arow * 8 + (aku ^ (arow & 7))) << 4);
                LDSM4(ah[mt][0], ah[mt][1], ah[mt][2], ah[mt][3], stg + off);
                LDSM4(al[mt][0], al[mt][1], al[mt][2], al[mt][3], stg + 16384 + off);
            }
            #pragma unroll
            for (int nt = 0; nt < 4; nt++) {
                int brow = warp_c * 32 + nt * 8 + b_row_in;
                int bku  = kb + b_kseg;
                uint32_t off = (uint32_t)((brow * 8 + (bku ^ (brow & 7))) << 4);
                LDSM2(bh[nt][0], bh[nt][1], stg + 32768 + off);
                LDSM2(bl[nt][0], bl[nt][1], stg + 40960 + off);
            }
            #pragma unroll
            for (int mt = 0; mt < 2; mt++)
                #pragma unroll
                for (int nt = 0; nt < 4; nt++) {
                    mma_bf16(acc[mt][nt], ah[mt], bh[nt]);
                    mma_bf16(acc[mt][nt], al[mt], bh[nt]);
                    mma_bf16(acc[mt][nt], ah[mt], bl[nt]);
                }
        }
        __syncthreads();
    }

    // ---- epilogue: fp32 stores + bias (+ per-CTA deterministic stats) ----
    float s_loc[8], ss_loc[8];
    if (STATS) {
        #pragma unroll
        for (int i = 0; i < 8; i++) { s_loc[i] = 0.f; ss_loc[i] = 0.f; }
    }
    #pragma unroll
    for (int mt = 0; mt < 2; mt++) {
        #pragma unroll
        for (int nt = 0; nt < 4; nt++) {
            int r  = row0 + warp_r * 32 + mt * 16 + (lane >> 2);
            int cc = col0 + warp_c * 32 + nt * 8 + (lane & 3) * 2;
            float bx = bias[cc], by = bias[cc + 1];
            float v0 = acc[mt][nt][0] + bx, v1 = acc[mt][nt][1] + by;
            float v2 = acc[mt][nt][2] + bx, v3 = acc[mt][nt][3] + by;
            if (r < M) {
                *(float2*)&out[(size_t)r * ostride + cc] = make_float2(v0, v1);
                if (STATS) {
                    s_loc[nt*2]   += v0; ss_loc[nt*2]   += v0 * v0;
                    s_loc[nt*2+1] += v1; ss_loc[nt*2+1] += v1 * v1;
                }
            }
            if (r + 8 < M) {
                *(float2*)&out[(size_t)(r + 8) * ostride + cc] = make_float2(v2, v3);
                if (STATS) {
                    s_loc[nt*2]   += v2; ss_loc[nt*2]   += v2 * v2;
                    s_loc[nt*2+1] += v3; ss_loc[nt*2+1] += v3 * v3;
                }
            }
        }
    }
    if (STATS) {
        // reduce over the 8 lane-groups holding different rows (fixed order)
        #pragma unroll
        for (int i = 0; i < 8; i++) {
            #pragma unroll
            for (int st = 4; st < 32; st <<= 1) {
                s_loc[i]  += __shfl_xor_sync(0xFFFFFFFFu, s_loc[i],  st);
                ss_loc[i] += __shfl_xor_sync(0xFFFFFFFFu, ss_loc[i], st);
            }
        }
        float* sred = (float*)(dsm + 2 * STG_BYTES);   // [8w][64c] s, then ss
        __syncthreads();
        if (lane < 4) {
            #pragma unroll
            for (int i = 0; i < 8; i++) {
                int colg = warp_c * 32 + (i >> 1) * 8 + lane * 2 + (i & 1);
                sred[wid * 64 + colg]       = s_loc[i];
                sred[512 + wid * 64 + colg] = ss_loc[i];
            }
        }
        __syncthreads();
        if (tid < 64) {
            int col = tid;
            int wb  = (col >= 32) ? 4 : 0;
            float s  = sred[(wb+0)*64+col] + sred[(wb+1)*64+col]
                     + sred[(wb+2)*64+col] + sred[(wb+3)*64+col];
            float ss = sred[512+(wb+0)*64+col] + sred[512+(wb+1)*64+col]
                     + sred[512+(wb+2)*64+col] + sred[512+(wb+3)*64+col];
            g_stat[(size_t)blockIdx.x * 128 + col]      = s;
            g_stat[(size_t)blockIdx.x * 128 + 64 + col] = ss;
        }
    }
}

// ---------------------------------------------------------------------------
// Prep kernels
// ---------------------------------------------------------------------------
__global__ void tspl_kernel(const float* __restrict__ src,
                            __nv_bfloat16* __restrict__ dst, int K, int N)
{
    int idx = blockIdx.x * 256 + threadIdx.x;
    if (idx >= K * N) return;
    int k = idx / N, n = idx - k * N;
    float hi, lo; splitf(src[idx], hi, lo);
    dst[(size_t)n * 2 * K + k]     = __float2bfloat16(hi);
    dst[(size_t)n * 2 * K + K + k] = __float2bfloat16(lo);
}

__global__ __launch_bounds__(256) void x1split_kernel(const float* __restrict__ x1)
{
    size_t idx = (size_t)blockIdx.x * 256 + threadIdx.x;
    if (idx >= (size_t)M_UP * 32) return;
    size_t r = idx >> 5; int q = (int)(idx & 31);
    float4 v = *(const float4*)(x1 + r * 128 + q * 4);
    uint2 h, l; split4(v, h, l);
    ((uint2*)g_x1c)[r * 64 + q]      = h;
    ((uint2*)g_x1c)[r * 64 + 32 + q] = l;
}

__global__ __launch_bounds__(256) void build_xcat_kernel(
    const float* __restrict__ x2, const int* __restrict__ topi,
    const int* __restrict__ downi)
{
    size_t idx = (size_t)blockIdx.x * 256 + threadIdx.x;
    if (idx >= (size_t)M_CONV * 32) return;
    int q = (int)(idx & 31);
    size_t bi = idx >> 5;
    int b = (bi >= NHH) ? 1 : 0;
    int i = (int)(bi - (size_t)b * NHH);
    const float* hf = g_h + (size_t)b * NR * 448;   // flat [Nr*7][64]
    float4 v;
    if (q < 16) {
        if (i < NR) {
            int t = topi[i];
            v = ((const float4*)(hf + (size_t)t * 64))[q];
        } else {
            int jj = i - NR;
            int d0 = downi[jj * 2 + 0];
            int d1 = downi[jj * 2 + 1];
            float4 a = ((const float4*)(hf + (size_t)d0 * 64))[q];
            float4 c = ((const float4*)(hf + (size_t)d1 * 64))[q];
            v = make_float4(0.5f*(a.x+c.x), 0.5f*(a.y+c.y),
                            0.5f*(a.z+c.z), 0.5f*(a.w+c.w));
        }
    } else {
        v = ((const float4*)x2)[bi * 16 + (q - 16)];
    }
    uint2 h, l; split4(v, h, l);
    ((uint2*)g_xcc)[bi * 64 + q]      = h;
    ((uint2*)g_xcc)[bi * 64 + 32 + q] = l;
}

// bn1 + lrelu applied to g_y1, split -> g_y2c [M_CONV][2*64]
__global__ __launch_bounds__(256) void bn_split_kernel()
{
    size_t idx = (size_t)blockIdx.x * 256 + threadIdx.x;
    if (idx >= (size_t)M_CONV * 16) return;
    size_t r = idx >> 4; int q = (int)(idx & 15);
    int c = q * 4;
    float4 v = *(const float4*)(g_y1 + r * 64 + c);
    v.x = v.x * g_bn[c+0] + g_bn[64+c+0]; v.x = fmaxf(v.x, 0.2f * v.x);
    v.y = v.y * g_bn[c+1] + g_bn[64+c+1]; v.y = fmaxf(v.y, 0.2f * v.y);
    v.z = v.z * g_bn[c+2] + g_bn[64+c+2]; v.z = fmaxf(v.z, 0.2f * v.z);
    v.w = v.w * g_bn[c+3] + g_bn[64+c+3]; v.w = fmaxf(v.w, 0.2f * v.w);
    uint2 h, l; split4(v, h, l);
    ((uint2*)g_y2c)[r * 32 + q]      = h;
    ((uint2*)g_y2c)[r * 32 + 16 + q] = l;
}

// ---------------------------------------------------------------------------
// BN statistics: stage-2 reduce over CTAs, then finalize (all fixed order)
// ---------------------------------------------------------------------------
__global__ __launch_bounds__(128) void stats_reduce_kernel(int ncta)
{
    int col = threadIdx.x;            // 0..127 (s|ss concatenated)
    float acc = 0.f;
    for (int p = blockIdx.x; p < ncta; p += 128)
        acc += g_stat[(size_t)p * 128 + col];
    g_part[blockIdx.x * 128 + col] = acc;
}

__global__ void stats_final_kernel(const float* __restrict__ gamma,
                                   const float* __restrict__ beta)
{
    int c = threadIdx.x;
    if (c >= 64) return;
    float s = 0.f, ss = 0.f;
    for (int p = 0; p < 128; p++) {
        s  += g_part[p * 128 + c];
        ss += g_part[p * 128 + 64 + c];
    }
    const float inv = 1.0f / (float)M_CONV;
    float mean = s * inv;
    float var  = fmaxf(ss * inv - mean * mean, 0.f);
    float sc   = gamma[c] * rsqrtf(var + 1e-5f);
    g_bn[c]      = sc;
    g_bn[64 + c] = beta[c] - mean * sc;
}

// Final in-place bn2 + lrelu on d_out
__global__ __launch_bounds__(256) void bn_act_kernel(float* __restrict__ y)
{
    size_t idx = (size_t)blockIdx.x * 256 + threadIdx.x;
    if (idx >= (size_t)M_CONV * 16) return;
    int c = ((int)idx & 15) * 4;
    float4 v = ((float4*)y)[idx];
    v.x = v.x * g_bn[c+0] + g_bn[64+c+0]; v.x = fmaxf(v.x, 0.2f * v.x);
    v.y = v.y * g_bn[c+1] + g_bn[64+c+1]; v.y = fmaxf(v.y, 0.2f * v.y);
    v.z = v.z * g_bn[c+2] + g_bn[64+c+2]; v.z = fmaxf(v.z, 0.2f * v.z);
    v.w = v.w * g_bn[c+3] + g_bn[64+c+3]; v.w = fmaxf(v.w, 0.2f * v.w);
    ((float4*)y)[idx] = v;
}

// ---------------------------------------------------------------------------
extern "C" void kernel_launch(void* const* d_in, const int* in_sizes, int n_in,
                              void* d_out, int out_size)
{
    const float* x1    = (const float*)d_in[0];
    const float* x2    = (const float*)d_in[1];
    const int*   neigh = (const int*)  d_in[2];
    const int*   topi  = (const int*)  d_in[3];
    const int*   downi = (const int*)  d_in[4];
    const float* up_W  = (const float*)d_in[5];
    const float* up_b  = (const float*)d_in[6];
    const float* w1    = (const float*)d_in[7];
    const float* b1    = (const float*)d_in[8];
    const float* g1    = (const float*)d_in[9];
    const float* be1   = (const float*)d_in[10];
    const float* w2    = (const float*)d_in[11];
    const float* b2    = (const float*)d_in[12];
    const float* g2    = (const float*)d_in[13];
    const float* be2   = (const float*)d_in[14];
    float* out = (float*)d_out;

    void *p_x1c, *p_h, *p_xcc, *p_y1, *p_y2c, *p_wuc, *p_w1c, *p_w2c;
    cudaGetSymbolAddress(&p_x1c, g_x1c);
    cudaGetSymbolAddress(&p_h,   g_h);
    cudaGetSymbolAddress(&p_xcc, g_xcc);
    cudaGetSymbolAddress(&p_y1,  g_y1);
    cudaGetSymbolAddress(&p_y2c, g_y2c);
    cudaGetSymbolAddress(&p_wuc, g_wuc);
    cudaGetSymbolAddress(&p_w1c, g_w1c);
    cudaGetSymbolAddress(&p_w2c, g_w2c);

    // Opt-in dynamic smem (host-side config; idempotent)
    cudaFuncSetAttribute(mma_gemm<128, 1, false, false, true>,
                         cudaFuncAttributeMaxDynamicSharedMemorySize, SMEM_DYN);
    cudaFuncSetAttribute(mma_gemm<128, 7, true, true, false>,
                         cudaFuncAttributeMaxDynamicSharedMemorySize, SMEM_DYN);
    cudaFuncSetAttribute(mma_gemm<64, 7, true, true, false>,
                         cudaFuncAttributeMaxDynamicSharedMemorySize, SMEM_DYN);

    // 0) weight transpose+split, x1 split
    tspl_kernel<<<(128*448 + 255)/256, 256>>>(up_W, (__nv_bfloat16*)p_wuc, 128, 448);
    tspl_kernel<<<(896*64  + 255)/256, 256>>>(w1,   (__nv_bfloat16*)p_w1c, 896, 64);
    tspl_kernel<<<(448*64  + 255)/256, 256>>>(w2,   (__nv_bfloat16*)p_w2c, 448, 64);
    x1split_kernel<<<(int)(((size_t)M_UP*32 + 255)/256), 256>>>(x1);

    // 1) up GEMM: [M_UP x 448] = x1 @ up_W + up_b
    //    grid swapped: 7 col-tiles sharing an A block are launch-adjacent (L2 reuse)
    mma_gemm<128, 1, false, false, true>
        <<<dim3(7, (M_UP + 127)/128), 256, SMEM_DYN>>>(
        (const __nv_bfloat16*)p_x1c, (const __nv_bfloat16*)p_wuc,
        nullptr, up_b, (float*)p_h, M_UP, 448);

    // 2) upconv gather + concat + split
    build_xcat_kernel<<<(int)(((size_t)M_CONV*32 + 255)/256), 256>>>(x2, topi, downi);

    // 3) conv1 (gather GEMM, K=896) -> g_y1 (pre-BN) + fused stats partials
    mma_gemm<128, 7, true, true, false><<<dim3(NCTA_CONV, 1), 256, SMEM_DYN>>>(
        (const __nv_bfloat16*)p_xcc, (const __nv_bfloat16*)p_w1c,
        neigh, b1, (float*)p_y1, M_CONV, 64);

    // 4) bn1 stats finalize + split input for conv2
    stats_reduce_kernel<<<128, 128>>>(NCTA_CONV);
    stats_final_kernel<<<1, 64>>>(g1, be1);
    bn_split_kernel<<<(int)(((size_t)M_CONV*16 + 255)/256), 256>>>();

    // 5) conv2 (gather GEMM, K=448) -> d_out (pre-BN) + fused stats partials
    mma_gemm<64, 7, true, true, false><<<dim3(NCTA_CONV, 1), 256, SMEM_DYN>>>(
        (const __nv_bfloat16*)p_y2c, (const __nv_bfloat16*)p_w2c,
        neigh, b2, out, M_CONV, 64);

    // 6) bn2 stats finalize + final activation in place
    stats_reduce_kernel<<<128, 128>>>(NCTA_CONV);
    stats_final_kernel<<<1, 64>>>(g2, be2);
    bn_act_kernel<<<(int)(((size_t)M_CONV*16 + 255)/256), 256>>>(out);
}